// round 3
// baseline (speedup 1.0000x reference)
#include <cuda_runtime.h>

#define NB 512      // batch
#define NT 1024     // time steps
#define HID 64      // hidden
#define NG 192      // 3 * HID gates

// Scratch (static __device__ arrays; allocation-free per harness rules)
__device__ float g_h0[(size_t)NT * NB * HID];  // [t][b][j] layer outputs (ping)
__device__ float g_h1[(size_t)NT * NB * HID];  // (pong)

__device__ __forceinline__ float sigf(float x) {
    return __fdividef(1.f, 1.f + __expf(-x));
}
__device__ __forceinline__ float tanh_(float x) {
    return fmaf(2.f, sigf(2.f * x), -1.f);
}

// packed fp32x2 FMA: d = a*b + c (per 32-bit lane)
__device__ __forceinline__ unsigned long long ffma2(unsigned long long a,
                                                    unsigned long long b,
                                                    unsigned long long c) {
    unsigned long long d;
    asm("fma.rn.f32x2 %0, %1, %2, %3;" : "=l"(d) : "l"(a), "l"(b), "l"(c));
    return d;
}
__device__ __forceinline__ float f2sum(unsigned long long v) {
    return __uint_as_float((unsigned)v) + __uint_as_float((unsigned)(v >> 32));
}

// ---------------------------------------------------------------------------
// Fused GRU layer: input GEMM + recurrent scan in one persistent kernel.
// 128 blocks x 192 threads; block owns 4 batch rows. Thread g owns gate g:
// w_ih row AND w_hh row in packed f32x2 registers. h + staged inputs in smem.
// Gate order (torch): r=[0:64), z=[64:128), n=[128:192).
// L0: input dim = 5 (x is [B][T][5]); else input = previous h ([T][B][64]).
// ---------------------------------------------------------------------------
template <int L0>
__global__ __launch_bounds__(192, 1)
void k_fscan(const float* __restrict__ xin,
             const float* __restrict__ w_ih, const float* __restrict__ b_ih,
             const float* __restrict__ w_hh, const float* __restrict__ b_hh,
             float* __restrict__ hout, int store_all) {
    const int g = threadIdx.x;
    const int b0 = blockIdx.x * 4;
    __shared__ __align__(16) float h_sh[4][HID];
    __shared__ __align__(16) float x_sh[2][4][HID];  // L0 uses [.][r][c<5]
    __shared__ float rz_sh[2][4][HID];               // [r|z][row][j]

    // ---- weights into registers ----
    unsigned long long wih[32];
    float wih0[5];
    if (L0) {
#pragma unroll
        for (int c = 0; c < 5; c++) wih0[c] = w_ih[g * 5 + c];
    } else {
        const ulonglong2* wp = (const ulonglong2*)(w_ih + (size_t)g * HID);
#pragma unroll
        for (int k = 0; k < 16; k++) {
            ulonglong2 v = wp[k];
            wih[2 * k] = v.x; wih[2 * k + 1] = v.y;
        }
    }
    unsigned long long whh[32];
    {
        const ulonglong2* wp = (const ulonglong2*)(w_hh + (size_t)g * HID);
#pragma unroll
        for (int k = 0; k < 16; k++) {
            ulonglong2 v = wp[k];
            whh[2 * k] = v.x; whh[2 * k + 1] = v.y;
        }
    }
    const float bi = b_ih[g], bh = b_hh[g];

    for (int i = g; i < 4 * HID; i += NG) ((float*)h_sh)[i] = 0.f;

    // ---- prologue: stage t=0 into x_sh[0], t=1 into prefetch regs ----
    float4 pf = make_float4(0.f, 0.f, 0.f, 0.f);
    float pf0 = 0.f;
    if (L0) {
        if (g < 20) {
            int r = g / 5, c = g % 5;
            x_sh[0][r][c] = xin[(size_t)(b0 + r) * NT * 5 + c];
            pf0 = xin[((size_t)(b0 + r) * NT + 1) * 5 + c];
        }
    } else {
        if (g < 64) {
            ((float4*)&x_sh[0][0][0])[g] = ((const float4*)(xin + (size_t)b0 * HID))[g];
            pf = ((const float4*)(xin + ((size_t)NB + b0) * HID))[g];
        }
    }
    __syncthreads();

    for (int t = 0; t < NT; t++) {
        // ---- prefetch input tile for t+2 (distance-2, hides DRAM latency) ----
        float4 npf = make_float4(0.f, 0.f, 0.f, 0.f);
        float npf0 = 0.f;
        if (t + 2 < NT) {
            if (L0) {
                if (g < 20) {
                    int r = g / 5, c = g % 5;
                    npf0 = xin[((size_t)(b0 + r) * NT + (t + 2)) * 5 + c];
                }
            } else {
                if (g < 64)
                    npf = ((const float4*)(xin + ((size_t)(t + 2) * NB + b0) * HID))[g];
            }
        }

        const int cur = t & 1, nxt = (t + 1) & 1;
        float sih[4], shh[4];

        // ---- hidden-side dot: shh[r] = bh + w_hh[g] . h[r] ----
        {
            unsigned long long a0 = 0, a0b = 0, a1 = 0, a1b = 0;
            unsigned long long a2 = 0, a2b = 0, a3 = 0, a3b = 0;
            const ulonglong2* h0 = (const ulonglong2*)h_sh[0];
            const ulonglong2* h1 = (const ulonglong2*)h_sh[1];
            const ulonglong2* h2 = (const ulonglong2*)h_sh[2];
            const ulonglong2* h3 = (const ulonglong2*)h_sh[3];
#pragma unroll
            for (int k = 0; k < 16; k++) {
                ulonglong2 v0 = h0[k], v1 = h1[k], v2 = h2[k], v3 = h3[k];
                a0 = ffma2(whh[2 * k], v0.x, a0); a0b = ffma2(whh[2 * k + 1], v0.y, a0b);
                a1 = ffma2(whh[2 * k], v1.x, a1); a1b = ffma2(whh[2 * k + 1], v1.y, a1b);
                a2 = ffma2(whh[2 * k], v2.x, a2); a2b = ffma2(whh[2 * k + 1], v2.y, a2b);
                a3 = ffma2(whh[2 * k], v3.x, a3); a3b = ffma2(whh[2 * k + 1], v3.y, a3b);
            }
            shh[0] = bh + f2sum(a0) + f2sum(a0b);
            shh[1] = bh + f2sum(a1) + f2sum(a1b);
            shh[2] = bh + f2sum(a2) + f2sum(a2b);
            shh[3] = bh + f2sum(a3) + f2sum(a3b);
        }

        // ---- input-side dot: sih[r] = bi + w_ih[g] . x[r] ----
        if (L0) {
#pragma unroll
            for (int r = 0; r < 4; r++) {
                float acc = bi;
#pragma unroll
                for (int c = 0; c < 5; c++) acc += wih0[c] * x_sh[cur][r][c];
                sih[r] = acc;
            }
        } else {
            unsigned long long a0 = 0, a0b = 0, a1 = 0, a1b = 0;
            unsigned long long a2 = 0, a2b = 0, a3 = 0, a3b = 0;
            const ulonglong2* x0 = (const ulonglong2*)x_sh[cur][0];
            const ulonglong2* x1 = (const ulonglong2*)x_sh[cur][1];
            const ulonglong2* x2 = (const ulonglong2*)x_sh[cur][2];
            const ulonglong2* x3 = (const ulonglong2*)x_sh[cur][3];
#pragma unroll
            for (int k = 0; k < 16; k++) {
                ulonglong2 v0 = x0[k], v1 = x1[k], v2 = x2[k], v3 = x3[k];
                a0 = ffma2(wih[2 * k], v0.x, a0); a0b = ffma2(wih[2 * k + 1], v0.y, a0b);
                a1 = ffma2(wih[2 * k], v1.x, a1); a1b = ffma2(wih[2 * k + 1], v1.y, a1b);
                a2 = ffma2(wih[2 * k], v2.x, a2); a2b = ffma2(wih[2 * k + 1], v2.y, a2b);
                a3 = ffma2(wih[2 * k], v3.x, a3); a3b = ffma2(wih[2 * k + 1], v3.y, a3b);
            }
            sih[0] = bi + f2sum(a0) + f2sum(a0b);
            sih[1] = bi + f2sum(a1) + f2sum(a1b);
            sih[2] = bi + f2sum(a2) + f2sum(a2b);
            sih[3] = bi + f2sum(a3) + f2sum(a3b);
        }

        // ---- r and z gates ----
        if (g < 128) {
            const int which = g >> 6;  // 0 = r, 1 = z
            const int j = g & 63;
#pragma unroll
            for (int r = 0; r < 4; r++)
                rz_sh[which][r][j] = sigf(sih[r] + shh[r]);
        }

        // ---- stage prefetched tile (t+1) into the other smem buffer ----
        if (t + 1 < NT) {
            if (L0) {
                if (g < 20) { int r = g / 5, c = g % 5; x_sh[nxt][r][c] = pf0; }
            } else {
                if (g < 64) ((float4*)&x_sh[nxt][0][0])[g] = pf;
            }
        }
        __syncthreads();   // rz ready; all reads of h_sh done

        // ---- n gate + state update ----
        if (g >= 128) {
            const int j = g - 128;
            float* op = hout + ((size_t)t * NB + b0) * HID + j;
            const bool st = store_all || (t == NT - 1);
#pragma unroll
            for (int r = 0; r < 4; r++) {
                float n = tanh_(sih[r] + rz_sh[0][r][j] * shh[r]);
                float z = rz_sh[1][r][j];
                float hn = n + z * (h_sh[r][j] - n);
                h_sh[r][j] = hn;
                if (st) op[r * HID] = hn;
            }
        }
        __syncthreads();   // h_sh updated for next step
        pf = npf; pf0 = npf0;
    }
}

// ---------------------------------------------------------------------------
// Final FC on last timestep: out[b] = h[T-1][b][:] . w_fc + b_fc
// ---------------------------------------------------------------------------
__global__ void k_fc(const float* __restrict__ hin,
                     const float* __restrict__ w_fc,
                     const float* __restrict__ b_fc,
                     float* __restrict__ out) {
    int b = blockIdx.x * blockDim.x + threadIdx.x;
    if (b >= NB) return;
    const float* hp = hin + ((size_t)(NT - 1) * NB + b) * HID;
    float acc = b_fc[0];
#pragma unroll
    for (int k = 0; k < HID; k++) acc += hp[k] * w_fc[k];
    out[b] = acc;
}

// ---------------------------------------------------------------------------
extern "C" void kernel_launch(void* const* d_in, const int* in_sizes, int n_in,
                              void* d_out, int out_size) {
    const float* x     = (const float*)d_in[0];
    const float* w_ih0 = (const float*)d_in[1];
    const float* w_hh0 = (const float*)d_in[2];
    const float* b_ih0 = (const float*)d_in[3];
    const float* b_hh0 = (const float*)d_in[4];
    const float* w_ih  = (const float*)d_in[5];   // [4][192][64]
    const float* w_hh  = (const float*)d_in[6];   // [4][192][64]
    const float* b_ih  = (const float*)d_in[7];   // [4][192]
    const float* b_hh  = (const float*)d_in[8];   // [4][192]
    const float* w_fc  = (const float*)d_in[9];
    const float* b_fc  = (const float*)d_in[10];
    float* out = (float*)d_out;

    float *hA = nullptr, *hB = nullptr;
    cudaGetSymbolAddress((void**)&hA, g_h0);
    cudaGetSymbolAddress((void**)&hB, g_h1);

    // Layer 0 (input dim 5), fused GEMM+scan
    k_fscan<1><<<NB / 4, NG>>>(x, w_ih0, b_ih0, w_hh0, b_hh0, hA, 1);

    // Layers 1..4, fused
    float* hin = hA;
    float* hou = hB;
    for (int L = 0; L < 4; L++) {
        int last = (L == 3);
        k_fscan<0><<<NB / 4, NG>>>(hin,
                                   w_ih + (size_t)L * NG * HID, b_ih + L * NG,
                                   w_hh + (size_t)L * NG * HID, b_hh + L * NG,
                                   hou, !last);
        float* tmp = hin; hin = hou; hou = tmp;
    }

    // FC head on last timestep (hin holds the last layer's output)
    k_fc<<<2, 256>>>(hin, w_fc, b_fc, out);
}

// round 4
// speedup vs baseline: 1.1144x; 1.1144x over previous
#include <cuda_runtime.h>

#define NB 512      // batch
#define NT 1024     // time steps
#define HID 64      // hidden
#define NG 192      // 3 * HID gates
#define NTH 384     // threads per block (A: 0..191 hidden, B: 192..383 input)

// Scratch (static __device__ arrays; allocation-free per harness rules)
__device__ float g_h0[(size_t)NT * NB * HID];  // [t][b][j] layer outputs (ping)
__device__ float g_h1[(size_t)NT * NB * HID];  // (pong)

__device__ __forceinline__ float sigf(float x) {
    return __fdividef(1.f, 1.f + __expf(-x));
}
__device__ __forceinline__ float tanh_(float x) {
    return fmaf(2.f, sigf(2.f * x), -1.f);
}

// packed fp32x2 FMA: d = a*b + c (per 32-bit lane)
__device__ __forceinline__ unsigned long long ffma2(unsigned long long a,
                                                    unsigned long long b,
                                                    unsigned long long c) {
    unsigned long long d;
    asm("fma.rn.f32x2 %0, %1, %2, %3;" : "=l"(d) : "l"(a), "l"(b), "l"(c));
    return d;
}
__device__ __forceinline__ float f2sum(unsigned long long v) {
    return __uint_as_float((unsigned)v) + __uint_as_float((unsigned)(v >> 32));
}

// 4-row x 64 dot with packed weights: out[r] = bias + w . buf[r]
__device__ __forceinline__ void dot4(const unsigned long long* __restrict__ w2,
                                     const float* __restrict__ buf,  // [4][HID]
                                     float bias, float* out) {
    unsigned long long a0 = 0, a0b = 0, a1 = 0, a1b = 0;
    unsigned long long a2 = 0, a2b = 0, a3 = 0, a3b = 0;
    const ulonglong2* h0 = (const ulonglong2*)(buf);
    const ulonglong2* h1 = (const ulonglong2*)(buf + HID);
    const ulonglong2* h2 = (const ulonglong2*)(buf + 2 * HID);
    const ulonglong2* h3 = (const ulonglong2*)(buf + 3 * HID);
#pragma unroll
    for (int k = 0; k < 16; k++) {
        ulonglong2 v0 = h0[k], v1 = h1[k], v2 = h2[k], v3 = h3[k];
        a0 = ffma2(w2[2 * k], v0.x, a0); a0b = ffma2(w2[2 * k + 1], v0.y, a0b);
        a1 = ffma2(w2[2 * k], v1.x, a1); a1b = ffma2(w2[2 * k + 1], v1.y, a1b);
        a2 = ffma2(w2[2 * k], v2.x, a2); a2b = ffma2(w2[2 * k + 1], v2.y, a2b);
        a3 = ffma2(w2[2 * k], v3.x, a3); a3b = ffma2(w2[2 * k + 1], v3.y, a3b);
    }
    out[0] = bias + f2sum(a0) + f2sum(a0b);
    out[1] = bias + f2sum(a1) + f2sum(a1b);
    out[2] = bias + f2sum(a2) + f2sum(a2b);
    out[3] = bias + f2sum(a3) + f2sum(a3b);
}

// ---------------------------------------------------------------------------
// Fused GRU layer, warp-specialized. 128 blocks x 384 threads; block owns 4
// batch rows. Group A (0..191): hidden dot + r/z gates. Group B (192..383):
// input dot one step AHEAD (sih(t+1)) + x prefetch. n-gate/state update done
// by 256 threads. Gate order (torch): r=[0:64), z=[64:128), n=[128:192).
// L0: input dim = 5, x is [B][T][5]; else input = previous h, [T][B][64].
// ---------------------------------------------------------------------------
template <int L0>
__global__ __launch_bounds__(NTH, 1)
void k_fscan(const float* __restrict__ xin,
             const float* __restrict__ w_ih, const float* __restrict__ b_ih,
             const float* __restrict__ w_hh, const float* __restrict__ b_hh,
             float* __restrict__ hout, int store_all) {
    const int tid = threadIdx.x;
    const int b0 = blockIdx.x * 4;
    const bool isA = tid < NG;

    __shared__ __align__(16) float h_sh[4][HID];
    __shared__ __align__(16) float x_sh[2][4][HID];    // L0 uses cols < 5
    __shared__ float sih_sh[2][4][NG];                 // input-side preacts
    __shared__ float shh_n[4][HID];                    // hidden preact, n gates
    __shared__ float rz_sh[2][4][HID];                 // [r|z][row][j]

    // ---- weights into registers (one 64-reg set per thread) ----
    unsigned long long w2[32];
    float w5[5];
    float bias;
    if (isA) {
        const ulonglong2* wp = (const ulonglong2*)(w_hh + (size_t)tid * HID);
#pragma unroll
        for (int k = 0; k < 16; k++) {
            ulonglong2 v = wp[k];
            w2[2 * k] = v.x; w2[2 * k + 1] = v.y;
        }
        bias = b_hh[tid];
    } else {
        const int g = tid - NG;
        if (L0) {
#pragma unroll
            for (int c = 0; c < 5; c++) w5[c] = w_ih[g * 5 + c];
        } else {
            const ulonglong2* wp = (const ulonglong2*)(w_ih + (size_t)g * HID);
#pragma unroll
            for (int k = 0; k < 16; k++) {
                ulonglong2 v = wp[k];
                w2[2 * k] = v.x; w2[2 * k + 1] = v.y;
            }
        }
        bias = b_ih[g];
    }

    for (int i = tid; i < 4 * HID; i += NTH) ((float*)h_sh)[i] = 0.f;

    // ---- prologue: x(0) -> x_sh[1], x(1) -> x_sh[0] ----
    if (L0) {
        if (tid < 20) {
            int r = tid / 5, c = tid % 5;
            x_sh[1][r][c] = xin[(size_t)(b0 + r) * NT * 5 + c];
        } else if (tid < 40) {
            int u = tid - 20, r = u / 5, c = u % 5;
            x_sh[0][r][c] = xin[((size_t)(b0 + r) * NT + 1) * 5 + c];
        }
    } else {
        if (tid < 64) {
            ((float4*)&x_sh[1][0][0])[tid] =
                ((const float4*)(xin + (size_t)b0 * HID))[tid];
        } else if (tid < 128) {
            int u = tid - 64;
            ((float4*)&x_sh[0][0][0])[u] =
                ((const float4*)(xin + ((size_t)NB + b0) * HID))[u];
        }
    }
    __syncthreads();

    // ---- prologue: sih(0) -> sih_sh[0] (group B) ----
    if (!isA) {
        const int g = tid - NG;
        float s[4];
        if (L0) {
#pragma unroll
            for (int r = 0; r < 4; r++) {
                float acc = bias;
#pragma unroll
                for (int c = 0; c < 5; c++) acc += w5[c] * x_sh[1][r][c];
                s[r] = acc;
            }
        } else {
            dot4(w2, &x_sh[1][0][0], bias, s);
        }
#pragma unroll
        for (int r = 0; r < 4; r++) sih_sh[0][r][g] = s[r];
    }
    __syncthreads();

    for (int t = 0; t < NT; t++) {
        const int p = t & 1;

        if (isA) {
            // ---- hidden dot ----
            float shh[4];
            dot4(w2, &h_sh[0][0], bias, shh);
            if (tid < 128) {
                // r/z gates: needs only own shh + sih from previous iteration
                const int which = tid >> 6;   // 0 = r, 1 = z
                const int j = tid & 63;
#pragma unroll
                for (int r = 0; r < 4; r++)
                    rz_sh[which][r][j] = sigf(sih_sh[p][r][tid] + shh[r]);
            } else {
                const int j = tid - 128;
#pragma unroll
                for (int r = 0; r < 4; r++) shh_n[r][j] = shh[r];
            }
        } else {
            const int g = tid - NG;
            // ---- prefetch x(t+2) ----
            float4 pf;
            float pf0;
            const bool do_pf = (t + 2 < NT);
            if (do_pf) {
                if (L0) {
                    if (g < 20)
                        pf0 = xin[((size_t)(b0 + g / 5) * NT + (t + 2)) * 5 + g % 5];
                } else {
                    if (g < 64)
                        pf = ((const float4*)(xin + ((size_t)(t + 2) * NB + b0) * HID))[g];
                }
            }
            // ---- input dot for t+1 ----
            if (t + 1 < NT) {
                float s[4];
                if (L0) {
#pragma unroll
                    for (int r = 0; r < 4; r++) {
                        float acc = bias;
#pragma unroll
                        for (int c = 0; c < 5; c++) acc += w5[c] * x_sh[p][r][c];
                        s[r] = acc;
                    }
                } else {
                    dot4(w2, &x_sh[p][0][0], bias, s);
                }
#pragma unroll
                for (int r = 0; r < 4; r++) sih_sh[p ^ 1][r][g] = s[r];
            }
            // ---- stage prefetched x(t+2) into x_sh[p^1] ----
            if (do_pf) {
                if (L0) {
                    if (g < 20) x_sh[p ^ 1][g / 5][g % 5] = pf0;
                } else {
                    if (g < 64) ((float4*)&x_sh[p ^ 1][0][0])[g] = pf;
                }
            }
        }
        __syncthreads();   // rz_sh + shh_n ready; h_sh reads done

        // ---- n gate + state update: 256 threads, one element each ----
        if (tid >= 128) {
            const int u = tid - 128;
            const int r = u >> 6, j = u & 63;
            float sh = shh_n[r][j];
            float n = tanh_(sih_sh[p][r][128 + j] + rz_sh[0][r][j] * sh);
            float z = rz_sh[1][r][j];
            float hp = h_sh[r][j];
            float hn = n + z * (hp - n);
            h_sh[r][j] = hn;
            if (store_all || t == NT - 1)
                hout[((size_t)t * NB + b0 + r) * HID + j] = hn;
        }
        __syncthreads();   // h_sh updated for next step
    }
}

// ---------------------------------------------------------------------------
// Final FC on last timestep: out[b] = h[T-1][b][:] . w_fc + b_fc
// ---------------------------------------------------------------------------
__global__ void k_fc(const float* __restrict__ hin,
                     const float* __restrict__ w_fc,
                     const float* __restrict__ b_fc,
                     float* __restrict__ out) {
    int b = blockIdx.x * blockDim.x + threadIdx.x;
    if (b >= NB) return;
    const float* hp = hin + ((size_t)(NT - 1) * NB + b) * HID;
    float acc = b_fc[0];
#pragma unroll
    for (int k = 0; k < HID; k++) acc += hp[k] * w_fc[k];
    out[b] = acc;
}

// ---------------------------------------------------------------------------
extern "C" void kernel_launch(void* const* d_in, const int* in_sizes, int n_in,
                              void* d_out, int out_size) {
    const float* x     = (const float*)d_in[0];
    const float* w_ih0 = (const float*)d_in[1];
    const float* w_hh0 = (const float*)d_in[2];
    const float* b_ih0 = (const float*)d_in[3];
    const float* b_hh0 = (const float*)d_in[4];
    const float* w_ih  = (const float*)d_in[5];   // [4][192][64]
    const float* w_hh  = (const float*)d_in[6];   // [4][192][64]
    const float* b_ih  = (const float*)d_in[7];   // [4][192]
    const float* b_hh  = (const float*)d_in[8];   // [4][192]
    const float* w_fc  = (const float*)d_in[9];
    const float* b_fc  = (const float*)d_in[10];
    float* out = (float*)d_out;

    float *hA = nullptr, *hB = nullptr;
    cudaGetSymbolAddress((void**)&hA, g_h0);
    cudaGetSymbolAddress((void**)&hB, g_h1);

    // Layer 0 (input dim 5), fused
    k_fscan<1><<<NB / 4, NTH>>>(x, w_ih0, b_ih0, w_hh0, b_hh0, hA, 1);

    // Layers 1..4, fused
    float* hin = hA;
    float* hou = hB;
    for (int L = 0; L < 4; L++) {
        int last = (L == 3);
        k_fscan<0><<<NB / 4, NTH>>>(hin,
                                    w_ih + (size_t)L * NG * HID, b_ih + L * NG,
                                    w_hh + (size_t)L * NG * HID, b_hh + L * NG,
                                    hou, !last);
        float* tmp = hin; hin = hou; hou = tmp;
    }

    // FC head on last timestep (hin holds the last layer's output)
    k_fc<<<2, 256>>>(hin, w_fc, b_fc, out);
}